// round 2
// baseline (speedup 1.0000x reference)
#include <cuda_runtime.h>
#include <math.h>

#define BB    2
#define LL    8
#define NPTS  256
#define MM    2048          // LL*NPTS
#define DIMF  512
#define HEADS 8
#define DHD   64
#define INNER 512           // HEADS*DHD
#define QKVD  1536
#define ROWS  (BB*MM)       // 4096

// scratch (allocation-free rule: __device__ globals)
__device__ float g_normed[ROWS * DIMF];
__device__ float g_qkv[ROWS * QKVD];
__device__ float g_outpre[ROWS * INNER];

// ---------------------------------------------------------------- LayerNorm
__global__ void ln_kernel(const float* __restrict__ x,
                          const float* __restrict__ gamma,
                          const float* __restrict__ beta) {
    int row = blockIdx.x;
    int t = threadIdx.x;
    const float* xr = x + (size_t)row * DIMF;
    float v0 = xr[t], v1 = xr[t + 256];
    float s = v0 + v1, ss = v0 * v0 + v1 * v1;
    #pragma unroll
    for (int o = 16; o > 0; o >>= 1) {
        s  += __shfl_xor_sync(0xffffffffu, s, o);
        ss += __shfl_xor_sync(0xffffffffu, ss, o);
    }
    __shared__ float ws[8], wss[8];
    if ((t & 31) == 0) { ws[t >> 5] = s; wss[t >> 5] = ss; }
    __syncthreads();
    float S = 0.f, SS = 0.f;
    #pragma unroll
    for (int i = 0; i < 8; i++) { S += ws[i]; SS += wss[i]; }
    float mean = S * (1.0f / DIMF);
    float var  = SS * (1.0f / DIMF) - mean * mean;
    float inv  = rsqrtf(var + 1e-5f);
    float* o = g_normed + (size_t)row * DIMF;
    o[t]       = (v0 - mean) * inv * gamma[t]       + beta[t];
    o[t + 256] = (v1 - mean) * inv * gamma[t + 256] + beta[t + 256];
}

// ---------------------------------------------------------------- SGEMM 64x64x16
// STAGE 0: g_normed[4096,512] @ w_qkv[512,1536] -> g_qkv
// STAGE 1: g_outpre[4096,512] @ w_out[512,512] + bias, exact GELU, + residual -> d_out
template <int STAGE>
__global__ void sgemm_kernel(const float* __restrict__ Bmat,
                             const float* __restrict__ bias,
                             const float* __restrict__ resid,
                             float* __restrict__ CoutParam,
                             int N) {
    const float* A = (STAGE == 0) ? g_normed : g_outpre;
    float* C       = (STAGE == 0) ? g_qkv    : CoutParam;
    __shared__ float As[16 * 64];   // [k][m]
    __shared__ float Bs[16 * 64];   // [k][n]
    int m0 = blockIdx.y * 64, n0 = blockIdx.x * 64;
    int t = threadIdx.x, ty = t >> 4, tx = t & 15;
    float acc[4][4] = {};
    for (int k0 = 0; k0 < 512; k0 += 16) {
        #pragma unroll
        for (int i = 0; i < 4; i++) {
            int e = t + i * 256; int r = e >> 4, c = e & 15;
            As[c * 64 + r] = A[(size_t)(m0 + r) * 512 + k0 + c];
        }
        #pragma unroll
        for (int i = 0; i < 4; i++) {
            int e = t + i * 256; int r = e >> 6, c = e & 63;
            Bs[r * 64 + c] = Bmat[(size_t)(k0 + r) * N + n0 + c];
        }
        __syncthreads();
        #pragma unroll
        for (int kk = 0; kk < 16; kk++) {
            float4 a4 = *(const float4*)&As[kk * 64 + ty * 4];
            float4 b4 = *(const float4*)&Bs[kk * 64 + tx * 4];
            float av[4] = {a4.x, a4.y, a4.z, a4.w};
            float bv[4] = {b4.x, b4.y, b4.z, b4.w};
            #pragma unroll
            for (int i = 0; i < 4; i++)
                #pragma unroll
                for (int j = 0; j < 4; j++)
                    acc[i][j] = fmaf(av[i], bv[j], acc[i][j]);
        }
        __syncthreads();
    }
    #pragma unroll
    for (int i = 0; i < 4; i++) {
        int row = m0 + ty * 4 + i;
        #pragma unroll
        for (int j = 0; j < 4; j++) {
            int col = n0 + tx * 4 + j;
            float x = acc[i][j];
            if (STAGE == 1) {
                x += bias[col];
                x = 0.5f * x * (1.0f + erff(x * 0.70710678118654752f));
                x += resid[(size_t)row * N + col];
            }
            C[(size_t)row * N + col] = x;
        }
    }
}

// ---------------------------------------------------------------- flash attention + xyz agg
// block: (b,h) x 64-query tile.  smem: Q[k][r], K[k][c] (reused as P[c][r], stride 68),
// V[c][d], xyz_i, xyz_j.
#define ATTN_SMEM ((64 * 64 + 64 * 68 + 64 * 64 + 64 * 4 + 64 * 4) * 4)

__global__ void attn_kernel(const float* __restrict__ xyzs,
                            const float* __restrict__ w_sp) {
    extern __shared__ float sm[];
    float* qs = sm;                  // 64*64, [k][row], Q pre-scaled
    float* kp = qs + 64 * 64;        // 64*68 region: K as [k][col] stride 64, then P as [c][row] stride 68
    float* vs = kp + 64 * 68;        // 64*64, [c][d]
    float* xi = vs + 64 * 64;        // 64*4
    float* xj = xi + 64 * 4;         // 64*4

    int bh = blockIdx.y;
    int b = bh >> 3, h = bh & 7;
    int i0 = blockIdx.x * 64;
    int t = threadIdx.x, ty = t >> 4, tx = t & 15;
    int lane = t & 31;

    const float* qkvb = g_qkv + (size_t)b * MM * QKVD;
    const float* xyzb = xyzs + (size_t)b * MM * 3;

    // Q tile load (fold in softmax scale 1/sqrt(64))
    {
        int r = t >> 2, kc = (t & 3) * 16;
        const float* gq = qkvb + (size_t)(i0 + r) * QKVD + h * DHD + kc;
        #pragma unroll
        for (int u = 0; u < 4; u++) {
            float4 v = *(const float4*)(gq + u * 4);
            qs[(kc + u * 4 + 0) * 64 + r] = v.x * 0.125f;
            qs[(kc + u * 4 + 1) * 64 + r] = v.y * 0.125f;
            qs[(kc + u * 4 + 2) * 64 + r] = v.z * 0.125f;
            qs[(kc + u * 4 + 3) * 64 + r] = v.w * 0.125f;
        }
    }
    if (t < 64) {
        xi[t * 4 + 0] = xyzb[(i0 + t) * 3 + 0];
        xi[t * 4 + 1] = xyzb[(i0 + t) * 3 + 1];
        xi[t * 4 + 2] = xyzb[(i0 + t) * 3 + 2];
        xi[t * 4 + 3] = 0.f;
    }

    float acc[4][4] = {};
    float axyz[4] = {0.f, 0.f, 0.f, 0.f};
    float mrow[4] = {-1e30f, -1e30f, -1e30f, -1e30f};
    float lrow[4] = {0.f, 0.f, 0.f, 0.f};

    for (int jt = 0; jt < 32; jt++) {
        int j0 = jt * 64;
        __syncthreads();   // previous iter's P readers done before K overwrites
        {
            int r = t >> 2, kc = (t & 3) * 16;
            const float* gk = qkvb + (size_t)(j0 + r) * QKVD + INNER + h * DHD + kc;
            const float* gv = qkvb + (size_t)(j0 + r) * QKVD + 2 * INNER + h * DHD + kc;
            #pragma unroll
            for (int u = 0; u < 4; u++) {
                float4 k4 = *(const float4*)(gk + u * 4);
                kp[(kc + u * 4 + 0) * 64 + r] = k4.x;
                kp[(kc + u * 4 + 1) * 64 + r] = k4.y;
                kp[(kc + u * 4 + 2) * 64 + r] = k4.z;
                kp[(kc + u * 4 + 3) * 64 + r] = k4.w;
                *(float4*)&vs[r * 64 + kc + u * 4] = *(const float4*)(gv + u * 4);
            }
        }
        if (t < 64) {
            xj[t * 4 + 0] = xyzb[(j0 + t) * 3 + 0];
            xj[t * 4 + 1] = xyzb[(j0 + t) * 3 + 1];
            xj[t * 4 + 2] = xyzb[(j0 + t) * 3 + 2];
        }
        __syncthreads();

        // S = Q K^T (scale already in Q)
        float s[4][4] = {};
        #pragma unroll 8
        for (int kk = 0; kk < 64; kk++) {
            float4 a4 = *(const float4*)&qs[kk * 64 + ty * 4];
            float4 b4 = *(const float4*)&kp[kk * 64 + tx * 4];
            float av[4] = {a4.x, a4.y, a4.z, a4.w};
            float bv[4] = {b4.x, b4.y, b4.z, b4.w};
            #pragma unroll
            for (int i = 0; i < 4; i++)
                #pragma unroll
                for (int j = 0; j < 4; j++)
                    s[i][j] = fmaf(av[i], bv[j], s[i][j]);
        }
        __syncthreads();   // done reading K; kp becomes P buffer

        // online softmax (row group = 16 lanes sharing ty)
        #pragma unroll
        for (int i = 0; i < 4; i++) {
            float mi = fmaxf(fmaxf(s[i][0], s[i][1]), fmaxf(s[i][2], s[i][3]));
            #pragma unroll
            for (int o = 8; o > 0; o >>= 1)
                mi = fmaxf(mi, __shfl_xor_sync(0xffffffffu, mi, o));
            float mn = fmaxf(mrow[i], mi);
            float alpha = __expf(mrow[i] - mn);
            mrow[i] = mn;
            float rs = 0.f;
            #pragma unroll
            for (int j = 0; j < 4; j++) {
                float p = __expf(s[i][j] - mn);
                s[i][j] = p;
                rs += p;
            }
            #pragma unroll
            for (int o = 8; o > 0; o >>= 1)
                rs += __shfl_xor_sync(0xffffffffu, rs, o);
            lrow[i] = lrow[i] * alpha + rs;
            #pragma unroll
            for (int j = 0; j < 4; j++) acc[i][j] *= alpha;
            axyz[i] *= alpha;
        }
        // store P (column-of-4-rows as float4; stride 68 keeps 16B alignment)
        #pragma unroll
        for (int j = 0; j < 4; j++) {
            float4 pv = make_float4(s[0][j], s[1][j], s[2][j], s[3][j]);
            *(float4*)&kp[(tx * 4 + j) * 68 + ty * 4] = pv;
        }
        __syncthreads();

        // O += P V ; xyz agg folded in (comp tx for tx<3)
        #pragma unroll 8
        for (int c = 0; c < 64; c++) {
            float4 p4 = *(const float4*)&kp[c * 68 + ty * 4];
            float4 v4 = *(const float4*)&vs[c * 64 + tx * 4];
            float pv[4] = {p4.x, p4.y, p4.z, p4.w};
            float vv[4] = {v4.x, v4.y, v4.z, v4.w};
            #pragma unroll
            for (int i = 0; i < 4; i++)
                #pragma unroll
                for (int j = 0; j < 4; j++)
                    acc[i][j] = fmaf(pv[i], vv[j], acc[i][j]);
            if (tx < 3) {
                float xc = xj[c * 4 + tx];
                #pragma unroll
                for (int i = 0; i < 4; i++)
                    axyz[i] = fmaf(pv[i], xc, axyz[i]);
            }
        }
    }

    // epilogue: O/l + ((attn@xyz)/l - xyz_i) @ w_sp  -> g_outpre[b, i, h*64+d]
    #pragma unroll
    for (int i = 0; i < 4; i++) {
        float invl = 1.0f / lrow[i];
        float a0 = __shfl_sync(0xffffffffu, axyz[i], (lane & 0x10) | 0);
        float a1 = __shfl_sync(0xffffffffu, axyz[i], (lane & 0x10) | 1);
        float a2 = __shfl_sync(0xffffffffu, axyz[i], (lane & 0x10) | 2);
        int r = ty * 4 + i;
        a0 = a0 * invl - xi[r * 4 + 0];
        a1 = a1 * invl - xi[r * 4 + 1];
        a2 = a2 * invl - xi[r * 4 + 2];
        float* orow = g_outpre + (size_t)(b * MM + i0 + r) * INNER + h * DHD;
        #pragma unroll
        for (int j = 0; j < 4; j++) {
            int d = tx * 4 + j;
            float disp = a0 * w_sp[d] + a1 * w_sp[64 + d] + a2 * w_sp[128 + d];
            orow[d] = acc[i][j] * invl + disp;
        }
    }
}

// ---------------------------------------------------------------- launch
extern "C" void kernel_launch(void* const* d_in, const int* in_sizes, int n_in,
                              void* d_out, int out_size) {
    const float* xyzs     = (const float*)d_in[0];
    const float* features = (const float*)d_in[1];
    const float* gamma    = (const float*)d_in[2];
    const float* beta     = (const float*)d_in[3];
    const float* w_qkv    = (const float*)d_in[4];
    const float* w_sp     = (const float*)d_in[5];
    const float* w_out    = (const float*)d_in[6];
    const float* b_out    = (const float*)d_in[7];
    float* out = (float*)d_out;

    ln_kernel<<<ROWS, 256>>>(features, gamma, beta);
    sgemm_kernel<0><<<dim3(QKVD / 64, ROWS / 64), 256>>>(w_qkv, nullptr, nullptr, nullptr, QKVD);
    cudaFuncSetAttribute(attn_kernel, cudaFuncAttributeMaxDynamicSharedMemorySize, ATTN_SMEM);
    attn_kernel<<<dim3(MM / 64, BB * HEADS), 256, ATTN_SMEM>>>(xyzs, w_sp);
    sgemm_kernel<1><<<dim3(DIMF / 64, ROWS / 64), 256>>>(w_out, b_out, features, out, DIMF);
}

// round 5
// speedup vs baseline: 2.4588x; 2.4588x over previous
#include <cuda_runtime.h>
#include <math.h>

#define BB    2
#define MM    2048
#define DIMF  512
#define HEADS 8
#define DHD   64
#define INNER 512
#define QKVD  1536
#define ROWS  (BB*MM)       // 4096

__device__ float g_normed[ROWS * DIMF];
__device__ float g_qkv[ROWS * QKVD];
__device__ float g_outpre[ROWS * INNER];

__device__ __forceinline__ void mma_tf32(float c[4],
                                         unsigned a0, unsigned a1, unsigned a2, unsigned a3,
                                         unsigned b0, unsigned b1) {
    asm volatile(
        "mma.sync.aligned.m16n8k8.row.col.f32.tf32.tf32.f32 "
        "{%0,%1,%2,%3}, {%4,%5,%6,%7}, {%8,%9}, {%0,%1,%2,%3};\n"
        : "+f"(c[0]), "+f"(c[1]), "+f"(c[2]), "+f"(c[3])
        : "r"(a0), "r"(a1), "r"(a2), "r"(a3), "r"(b0), "r"(b1));
}
__device__ __forceinline__ unsigned f2u(float x) { return __float_as_uint(x); }

// ---------------------------------------------------------------- LayerNorm
__global__ void ln_kernel(const float* __restrict__ x,
                          const float* __restrict__ gamma,
                          const float* __restrict__ beta) {
    int row = blockIdx.x;
    int t = threadIdx.x;
    const float* xr = x + (size_t)row * DIMF;
    float v0 = xr[t], v1 = xr[t + 256];
    float s = v0 + v1, ss = v0 * v0 + v1 * v1;
    #pragma unroll
    for (int o = 16; o > 0; o >>= 1) {
        s  += __shfl_xor_sync(0xffffffffu, s, o);
        ss += __shfl_xor_sync(0xffffffffu, ss, o);
    }
    __shared__ float ws[8], wss[8];
    if ((t & 31) == 0) { ws[t >> 5] = s; wss[t >> 5] = ss; }
    __syncthreads();
    float S = 0.f, SS = 0.f;
    #pragma unroll
    for (int i = 0; i < 8; i++) { S += ws[i]; SS += wss[i]; }
    float mean = S * (1.0f / DIMF);
    float var  = SS * (1.0f / DIMF) - mean * mean;
    float inv  = rsqrtf(var + 1e-5f);
    float* o = g_normed + (size_t)row * DIMF;
    o[t]       = (v0 - mean) * inv * gamma[t]       + beta[t];
    o[t + 256] = (v1 - mean) * inv * gamma[t + 256] + beta[t + 256];
}

// ---------------------------------------------------------------- tf32 GEMM 128x128, k-chunk 32
// STAGE 0: g_normed[4096,512] @ w_qkv[512,1536] -> g_qkv
// STAGE 1: g_outpre[4096,512] @ w_out[512,512] + bias, GELU, + residual -> out
#define AS_STRIDE 36
#define BS_STRIDE 136
template <int STAGE>
__global__ void gemm_tf32(const float* __restrict__ Bmat,
                          const float* __restrict__ bias,
                          const float* __restrict__ resid,
                          float* __restrict__ CoutParam,
                          int N) {
    const float* A = (STAGE == 0) ? g_normed : g_outpre;
    float* C       = (STAGE == 0) ? g_qkv    : CoutParam;
    __shared__ float As[128 * AS_STRIDE];   // [m][k]
    __shared__ float Bs[32 * BS_STRIDE];    // [k][n]
    int m0 = blockIdx.y * 128, n0 = blockIdx.x * 128;
    int t = threadIdx.x;
    int w = t >> 5, lane = t & 31;
    int wm = w >> 1, wn = w & 1;            // warp grid 4x2, warp tile 32x64
    int g = lane >> 2, tq = lane & 3;

    float acc[2][8][4] = {};

    for (int k0 = 0; k0 < 512; k0 += 32) {
        __syncthreads();
        #pragma unroll
        for (int i = 0; i < 4; i++) {
            int lin = t + i * 256;
            int r = lin >> 3, c4 = lin & 7;
            *(float4*)&As[r * AS_STRIDE + c4 * 4] =
                *(const float4*)&A[(size_t)(m0 + r) * 512 + k0 + c4 * 4];
        }
        #pragma unroll
        for (int i = 0; i < 4; i++) {
            int lin = t + i * 256;
            int r = lin >> 5, c4 = lin & 31;
            *(float4*)&Bs[r * BS_STRIDE + c4 * 4] =
                *(const float4*)&Bmat[(size_t)(k0 + r) * N + n0 + c4 * 4];
        }
        __syncthreads();
        #pragma unroll
        for (int kk = 0; kk < 4; kk++) {
            unsigned a[2][4];
            #pragma unroll
            for (int mt = 0; mt < 2; mt++) {
                int br = 32 * wm + 16 * mt;
                a[mt][0] = f2u(As[(br + g)     * AS_STRIDE + 8 * kk + tq]);
                a[mt][1] = f2u(As[(br + 8 + g) * AS_STRIDE + 8 * kk + tq]);
                a[mt][2] = f2u(As[(br + g)     * AS_STRIDE + 8 * kk + tq + 4]);
                a[mt][3] = f2u(As[(br + 8 + g) * AS_STRIDE + 8 * kk + tq + 4]);
            }
            #pragma unroll
            for (int nt = 0; nt < 8; nt++) {
                int bc = 64 * wn + 8 * nt + g;
                unsigned b0 = f2u(Bs[(8 * kk + tq)     * BS_STRIDE + bc]);
                unsigned b1 = f2u(Bs[(8 * kk + tq + 4) * BS_STRIDE + bc]);
                mma_tf32(acc[0][nt], a[0][0], a[0][1], a[0][2], a[0][3], b0, b1);
                mma_tf32(acc[1][nt], a[1][0], a[1][1], a[1][2], a[1][3], b0, b1);
            }
        }
    }

    #pragma unroll
    for (int mt = 0; mt < 2; mt++) {
        #pragma unroll
        for (int rr = 0; rr < 2; rr++) {
            int row = m0 + 32 * wm + 16 * mt + g + 8 * rr;
            #pragma unroll
            for (int nt = 0; nt < 8; nt++) {
                int col = n0 + 64 * wn + 8 * nt + 2 * tq;
                float x0 = acc[mt][nt][2 * rr + 0];
                float x1 = acc[mt][nt][2 * rr + 1];
                if (STAGE == 1) {
                    x0 += bias[col];
                    x1 += bias[col + 1];
                    x0 = 0.5f * x0 * (1.0f + erff(x0 * 0.70710678118654752f));
                    x1 = 0.5f * x1 * (1.0f + erff(x1 * 0.70710678118654752f));
                    x0 += resid[(size_t)row * N + col];
                    x1 += resid[(size_t)row * N + col + 1];
                }
                *(float2*)&C[(size_t)row * N + col] = make_float2(x0, x1);
            }
        }
    }
}

// ---------------------------------------------------------------- tf32 flash attention + xyz agg
// 128 threads = 4 warps, each warp owns 16 query rows. Q frags in registers.
// K smem [j][d] stride 68 (reused as P [q][j] stride 68), V_ext [j][0..71] stride 76
// (cols 64..66 = xyz_j so attn@xyz falls out of the PV mma).
#define KP_STRIDE 68
#define VS_STRIDE 76
__global__ void attn_kernel(const float* __restrict__ xyzs,
                            const float* __restrict__ w_sp) {
    __shared__ float kp[64 * KP_STRIDE];
    __shared__ float vs[64 * VS_STRIDE];

    int bh = blockIdx.y;
    int b = bh >> 3, h = bh & 7;
    int i0 = blockIdx.x * 64;
    int t = threadIdx.x;
    int w = t >> 5, lane = t & 31;
    int g = lane >> 2, tq = lane & 3;

    const float* qkvb = g_qkv + (size_t)b * MM * QKVD;

    // preload Q fragments (fold in 1/sqrt(64) scale)
    unsigned qf[8][4];
    {
        int r0 = i0 + 16 * w + g;
        const float* qp0 = qkvb + (size_t)r0 * QKVD + h * DHD;
        const float* qp1 = qp0 + 8 * QKVD;
        #pragma unroll
        for (int k0 = 0; k0 < 8; k0++) {
            qf[k0][0] = f2u(qp0[8 * k0 + tq]     * 0.125f);
            qf[k0][1] = f2u(qp1[8 * k0 + tq]     * 0.125f);
            qf[k0][2] = f2u(qp0[8 * k0 + tq + 4] * 0.125f);
            qf[k0][3] = f2u(qp1[8 * k0 + tq + 4] * 0.125f);
        }
    }
    if (t < 64) {   // zero V_ext pad cols 67..71 (written once, never touched again)
        #pragma unroll
        for (int c = 67; c < 72; c++) vs[t * VS_STRIDE + c] = 0.f;
    }

    float of[9][4] = {};
    float m0 = -1e30f, m1 = -1e30f, l0 = 0.f, l1 = 0.f;

    for (int jt = 0; jt < 32; jt++) {
        int j0 = jt * 64;
        __syncthreads();    // previous iteration's P/V readers done
        {
            int r = t >> 1, dc = (t & 1) * 32;
            const float* gk = qkvb + (size_t)(j0 + r) * QKVD + INNER + h * DHD + dc;
            const float* gv = gk + INNER;
            #pragma unroll
            for (int u = 0; u < 8; u++) {
                *(float4*)&kp[r * KP_STRIDE + dc + u * 4] = *(const float4*)(gk + u * 4);
                *(float4*)&vs[r * VS_STRIDE + dc + u * 4] = *(const float4*)(gv + u * 4);
            }
        }
        if (t < 64) {
            const float* gx = xyzs + ((size_t)b * MM + j0 + t) * 3;
            vs[t * VS_STRIDE + 64] = gx[0];
            vs[t * VS_STRIDE + 65] = gx[1];
            vs[t * VS_STRIDE + 66] = gx[2];
        }
        __syncthreads();

        // S = Q K^T
        float sacc[8][4] = {};
        #pragma unroll
        for (int n = 0; n < 8; n++) {
            const float* kb = &kp[(8 * n + g) * KP_STRIDE];
            #pragma unroll
            for (int k0 = 0; k0 < 8; k0++) {
                unsigned b0 = f2u(kb[8 * k0 + tq]);
                unsigned b1 = f2u(kb[8 * k0 + tq + 4]);
                mma_tf32(sacc[n], qf[k0][0], qf[k0][1], qf[k0][2], qf[k0][3], b0, b1);
            }
        }

        // online softmax (rows g and g+8 of this warp's 16-row slice)
        float lm0 = -1e30f, lm1 = -1e30f;
        #pragma unroll
        for (int n = 0; n < 8; n++) {
            lm0 = fmaxf(lm0, fmaxf(sacc[n][0], sacc[n][1]));
            lm1 = fmaxf(lm1, fmaxf(sacc[n][2], sacc[n][3]));
        }
        #pragma unroll
        for (int o = 1; o < 4; o <<= 1) {
            lm0 = fmaxf(lm0, __shfl_xor_sync(0xffffffffu, lm0, o));
            lm1 = fmaxf(lm1, __shfl_xor_sync(0xffffffffu, lm1, o));
        }
        float mn0 = fmaxf(m0, lm0), mn1 = fmaxf(m1, lm1);
        float al0 = __expf(m0 - mn0), al1 = __expf(m1 - mn1);
        m0 = mn0; m1 = mn1;
        float rs0 = 0.f, rs1 = 0.f;
        #pragma unroll
        for (int n = 0; n < 8; n++) {
            sacc[n][0] = __expf(sacc[n][0] - mn0);
            sacc[n][1] = __expf(sacc[n][1] - mn0);
            sacc[n][2] = __expf(sacc[n][2] - mn1);
            sacc[n][3] = __expf(sacc[n][3] - mn1);
            rs0 += sacc[n][0] + sacc[n][1];
            rs1 += sacc[n][2] + sacc[n][3];
        }
        #pragma unroll
        for (int o = 1; o < 4; o <<= 1) {
            rs0 += __shfl_xor_sync(0xffffffffu, rs0, o);
            rs1 += __shfl_xor_sync(0xffffffffu, rs1, o);
        }
        l0 = l0 * al0 + rs0;
        l1 = l1 * al1 + rs1;
        #pragma unroll
        for (int n = 0; n < 9; n++) {
            of[n][0] *= al0; of[n][1] *= al0;
            of[n][2] *= al1; of[n][3] *= al1;
        }

        __syncthreads();    // all warps done reading K before P overwrites it
        {
            int r0 = 16 * w + g, r1 = r0 + 8;
            #pragma unroll
            for (int n = 0; n < 8; n++) {
                int col = 8 * n + 2 * tq;
                *(float2*)&kp[r0 * KP_STRIDE + col] = make_float2(sacc[n][0], sacc[n][1]);
                *(float2*)&kp[r1 * KP_STRIDE + col] = make_float2(sacc[n][2], sacc[n][3]);
            }
        }
        // warp reads only its own P rows (STS->LDS warp-local ordering suffices)

        #pragma unroll
        for (int k0 = 0; k0 < 8; k0++) {
            int r0 = 16 * w + g, r1 = r0 + 8;
            unsigned a0 = f2u(kp[r0 * KP_STRIDE + 8 * k0 + tq]);
            unsigned a1 = f2u(kp[r1 * KP_STRIDE + 8 * k0 + tq]);
            unsigned a2 = f2u(kp[r0 * KP_STRIDE + 8 * k0 + tq + 4]);
            unsigned a3 = f2u(kp[r1 * KP_STRIDE + 8 * k0 + tq + 4]);
            const float* vb0 = &vs[(8 * k0 + tq)     * VS_STRIDE + g];
            const float* vb1 = &vs[(8 * k0 + tq + 4) * VS_STRIDE + g];
            #pragma unroll
            for (int n = 0; n < 9; n++) {
                unsigned b0 = f2u(vb0[8 * n]);
                unsigned b1 = f2u(vb1[8 * n]);
                mma_tf32(of[n], a0, a1, a2, a3, b0, b1);
            }
        }
    }

    // epilogue
    float invl0 = 1.0f / l0, invl1 = 1.0f / l1;
    int base = lane & ~3;
    // attn@xyz cols 64,65,66 live at (tq=0,reg0),(tq=0,reg1),(tq=1,reg0)
    float ax0_0 = __shfl_sync(0xffffffffu, of[8][0], base + 0);
    float ax1_0 = __shfl_sync(0xffffffffu, of[8][1], base + 0);
    float ax2_0 = __shfl_sync(0xffffffffu, of[8][0], base + 1);
    float ax0_1 = __shfl_sync(0xffffffffu, of[8][2], base + 0);
    float ax1_1 = __shfl_sync(0xffffffffu, of[8][3], base + 0);
    float ax2_1 = __shfl_sync(0xffffffffu, of[8][2], base + 1);

    int row0 = i0 + 16 * w + g, row1 = row0 + 8;
    const float* xq0 = xyzs + ((size_t)b * MM + row0) * 3;
    const float* xq1 = xyzs + ((size_t)b * MM + row1) * 3;
    float a00 = ax0_0 * invl0 - xq0[0];
    float a10 = ax1_0 * invl0 - xq0[1];
    float a20 = ax2_0 * invl0 - xq0[2];
    float a01 = ax0_1 * invl1 - xq1[0];
    float a11 = ax1_1 * invl1 - xq1[1];
    float a21 = ax2_1 * invl1 - xq1[2];

    float* orow0 = g_outpre + ((size_t)b * MM + row0) * INNER + h * DHD;
    float* orow1 = g_outpre + ((size_t)b * MM + row1) * INNER + h * DHD;
    #pragma unroll
    for (int n = 0; n < 8; n++) {
        int d = 8 * n + 2 * tq;
        float w00 = w_sp[d],       w01 = w_sp[d + 1];
        float w10 = w_sp[64 + d],  w11 = w_sp[64 + d + 1];
        float w20 = w_sp[128 + d], w21 = w_sp[128 + d + 1];
        float o00 = of[n][0] * invl0 + a00 * w00 + a10 * w10 + a20 * w20;
        float o01 = of[n][1] * invl0 + a00 * w01 + a10 * w11 + a20 * w21;
        float o10 = of[n][2] * invl1 + a01 * w00 + a11 * w10 + a21 * w20;
        float o11 = of[n][3] * invl1 + a01 * w01 + a11 * w11 + a21 * w21;
        *(float2*)&orow0[d] = make_float2(o00, o01);
        *(float2*)&orow1[d] = make_float2(o10, o11);
    }
}

// ---------------------------------------------------------------- launch
extern "C" void kernel_launch(void* const* d_in, const int* in_sizes, int n_in,
                              void* d_out, int out_size) {
    const float* xyzs     = (const float*)d_in[0];
    const float* features = (const float*)d_in[1];
    const float* gamma    = (const float*)d_in[2];
    const float* beta     = (const float*)d_in[3];
    const float* w_qkv    = (const float*)d_in[4];
    const float* w_sp     = (const float*)d_in[5];
    const float* w_out    = (const float*)d_in[6];
    const float* b_out    = (const float*)d_in[7];
    float* out = (float*)d_out;

    ln_kernel<<<ROWS, 256>>>(features, gamma, beta);
    gemm_tf32<0><<<dim3(QKVD / 128, ROWS / 128), 256>>>(w_qkv, nullptr, nullptr, nullptr, QKVD);
    attn_kernel<<<dim3(MM / 64, BB * HEADS), 128>>>(xyzs, w_sp);
    gemm_tf32<1><<<dim3(DIMF / 128, ROWS / 128), 256>>>(w_out, b_out, features, out, DIMF);
}

// round 8
// speedup vs baseline: 4.5377x; 1.8455x over previous
#include <cuda_runtime.h>
#include <math.h>

#define BB    2
#define MM    2048
#define DIMF  512
#define HEADS 8
#define DHD   64
#define INNER 512
#define QKVD  1536
#define ROWS  (BB*MM)       // 4096

__device__ float g_normed[ROWS * DIMF];
__device__ float g_qkv[ROWS * QKVD];
__device__ float g_outpre[ROWS * INNER];

__device__ __forceinline__ void mma_tf32(float c[4],
                                         unsigned a0, unsigned a1, unsigned a2, unsigned a3,
                                         unsigned b0, unsigned b1) {
    asm volatile(
        "mma.sync.aligned.m16n8k8.row.col.f32.tf32.tf32.f32 "
        "{%0,%1,%2,%3}, {%4,%5,%6,%7}, {%8,%9}, {%0,%1,%2,%3};\n"
        : "+f"(c[0]), "+f"(c[1]), "+f"(c[2]), "+f"(c[3])
        : "r"(a0), "r"(a1), "r"(a2), "r"(a3), "r"(b0), "r"(b1));
}
__device__ __forceinline__ unsigned f2u(float x) { return __float_as_uint(x); }

__device__ __forceinline__ void cp16(float* s, const float* g) {
    unsigned sa = (unsigned)__cvta_generic_to_shared(s);
    asm volatile("cp.async.ca.shared.global [%0], [%1], 16;\n" :: "r"(sa), "l"(g));
}
__device__ __forceinline__ void cp4(float* s, const float* g) {
    unsigned sa = (unsigned)__cvta_generic_to_shared(s);
    asm volatile("cp.async.ca.shared.global [%0], [%1], 4;\n" :: "r"(sa), "l"(g));
}
#define CP_COMMIT() asm volatile("cp.async.commit_group;\n" ::: "memory")
#define CP_WAIT(n)  asm volatile("cp.async.wait_group %0;\n" :: "n"(n) : "memory")

// ---------------------------------------------------------------- LayerNorm
__global__ void ln_kernel(const float* __restrict__ x,
                          const float* __restrict__ gamma,
                          const float* __restrict__ beta) {
    int row = blockIdx.x;
    int t = threadIdx.x;
    const float* xr = x + (size_t)row * DIMF;
    float v0 = xr[t], v1 = xr[t + 256];
    float s = v0 + v1, ss = v0 * v0 + v1 * v1;
    #pragma unroll
    for (int o = 16; o > 0; o >>= 1) {
        s  += __shfl_xor_sync(0xffffffffu, s, o);
        ss += __shfl_xor_sync(0xffffffffu, ss, o);
    }
    __shared__ float ws[8], wss[8];
    if ((t & 31) == 0) { ws[t >> 5] = s; wss[t >> 5] = ss; }
    __syncthreads();
    float S = 0.f, SS = 0.f;
    #pragma unroll
    for (int i = 0; i < 8; i++) { S += ws[i]; SS += wss[i]; }
    float mean = S * (1.0f / DIMF);
    float var  = SS * (1.0f / DIMF) - mean * mean;
    float inv  = rsqrtf(var + 1e-5f);
    float* o = g_normed + (size_t)row * DIMF;
    o[t]       = (v0 - mean) * inv * gamma[t]       + beta[t];
    o[t + 256] = (v1 - mean) * inv * gamma[t + 256] + beta[t + 256];
}

// ---------------------------------------------------------------- tf32 GEMM, 2-stage cp.async
// tile 128 x BN, k-chunk 32. STAGE0: BN=128 (grid 12x32). STAGE1: BN=64 (grid 8x32).
template <int BN>
__device__ __forceinline__ void gemm_load(const float* __restrict__ A,
                                          const float* __restrict__ Bmat,
                                          float* Asd, float* Bsd,
                                          int m0, int n0, int N, int k0, int t) {
    constexpr int BSTR = BN + 8;
    #pragma unroll
    for (int i = 0; i < 4; i++) {
        int lin = t + i * 256;
        int r = lin >> 3, c = (lin & 7) * 4;
        cp16(&Asd[r * 36 + c], &A[(size_t)(m0 + r) * 512 + k0 + c]);
    }
    #pragma unroll
    for (int i = 0; i < BN / 32; i++) {
        int lin = t + i * 256;
        int r = lin / (BN / 4), c = (lin % (BN / 4)) * 4;
        cp16(&Bsd[r * BSTR + c], &Bmat[(size_t)(k0 + r) * N + n0 + c]);
    }
}

template <int STAGE, int BN>
__global__ __launch_bounds__(256, 2) void gemm_tf32(const float* __restrict__ Bmat,
                          const float* __restrict__ bias,
                          const float* __restrict__ resid,
                          float* __restrict__ CoutP, int N) {
    constexpr int BSTR = BN + 8;
    constexpr int NT = BN / 16;           // n-subtiles per warp
    const float* A = (STAGE == 0) ? g_normed : g_outpre;
    float* C       = (STAGE == 0) ? g_qkv    : CoutP;
    extern __shared__ float smem[];
    float* As0 = smem;
    float* As1 = smem + 128 * 36;
    float* Bs0 = smem + 2 * 128 * 36;
    float* Bs1 = Bs0 + 32 * BSTR;

    int m0 = blockIdx.y * 128, n0 = blockIdx.x * BN;
    int t = threadIdx.x;
    int w = t >> 5, lane = t & 31;
    int wm = w >> 1, wn = w & 1;          // warp grid 4x2; warp tile 32 x BN/2
    int g = lane >> 2, tq = lane & 3;

    float acc[2][NT][4] = {};

    gemm_load<BN>(A, Bmat, As0, Bs0, m0, n0, N, 0, t);
    CP_COMMIT();

    for (int kc = 0; kc < 16; kc++) {
        float* Asc = (kc & 1) ? As1 : As0;
        float* Bsc = (kc & 1) ? Bs1 : Bs0;
        if (kc < 15) {
            float* Asn = (kc & 1) ? As0 : As1;
            float* Bsn = (kc & 1) ? Bs0 : Bs1;
            gemm_load<BN>(A, Bmat, Asn, Bsn, m0, n0, N, (kc + 1) * 32, t);
            CP_COMMIT();
            CP_WAIT(1);
        } else {
            CP_WAIT(0);
        }
        __syncthreads();
        #pragma unroll
        for (int kk = 0; kk < 4; kk++) {
            unsigned a[2][4];
            #pragma unroll
            for (int mt = 0; mt < 2; mt++) {
                int br = 32 * wm + 16 * mt;
                a[mt][0] = f2u(Asc[(br + g)     * 36 + 8 * kk + tq]);
                a[mt][1] = f2u(Asc[(br + 8 + g) * 36 + 8 * kk + tq]);
                a[mt][2] = f2u(Asc[(br + g)     * 36 + 8 * kk + tq + 4]);
                a[mt][3] = f2u(Asc[(br + 8 + g) * 36 + 8 * kk + tq + 4]);
            }
            #pragma unroll
            for (int nt = 0; nt < NT; nt++) {
                int bc = (BN / 2) * wn + 8 * nt + g;
                unsigned b0 = f2u(Bsc[(8 * kk + tq)     * BSTR + bc]);
                unsigned b1 = f2u(Bsc[(8 * kk + tq + 4) * BSTR + bc]);
                mma_tf32(acc[0][nt], a[0][0], a[0][1], a[0][2], a[0][3], b0, b1);
                mma_tf32(acc[1][nt], a[1][0], a[1][1], a[1][2], a[1][3], b0, b1);
            }
        }
        __syncthreads();
    }

    #pragma unroll
    for (int mt = 0; mt < 2; mt++) {
        #pragma unroll
        for (int rr = 0; rr < 2; rr++) {
            int row = m0 + 32 * wm + 16 * mt + g + 8 * rr;
            #pragma unroll
            for (int nt = 0; nt < NT; nt++) {
                int col = n0 + (BN / 2) * wn + 8 * nt + 2 * tq;
                float x0 = acc[mt][nt][2 * rr + 0];
                float x1 = acc[mt][nt][2 * rr + 1];
                if (STAGE == 1) {
                    x0 += bias[col];
                    x1 += bias[col + 1];
                    x0 = 0.5f * x0 * (1.0f + erff(x0 * 0.70710678118654752f));
                    x1 = 0.5f * x1 * (1.0f + erff(x1 * 0.70710678118654752f));
                    x0 += resid[(size_t)row * N + col];
                    x1 += resid[(size_t)row * N + col + 1];
                }
                *(float2*)&C[(size_t)row * N + col] = make_float2(x0, x1);
            }
        }
    }
}

// ---------------------------------------------------------------- tf32 flash attention + xyz agg
// 256 threads (8 warps), 128-query tile, 64-key tiles, 2-stage cp.async K/V,
// per-warp private P region (no cross-warp sync around P).
#define KSTR 68
#define VSTR 72
#define PSTR 68
#define ATTN_SMEM ((2*64*KSTR + 2*64*VSTR + 128*PSTR) * 4)

__device__ __forceinline__ void attn_load_stage(const float* __restrict__ kbase,
                                                const float* __restrict__ vbase,
                                                const float* __restrict__ xyzb,
                                                int j0, float* kb, float* vb, int t) {
    #pragma unroll
    for (int u = 0; u < 4; u++) {
        int idx = t + 256 * u;
        int r = idx >> 4, c = (idx & 15) * 4;
        cp16(&kb[r * KSTR + c], kbase + (size_t)(j0 + r) * QKVD + c);
        cp16(&vb[r * VSTR + c], vbase + (size_t)(j0 + r) * QKVD + c);
    }
    if (t < 64) {
        const float* gx = xyzb + (size_t)(j0 + t) * 3;
        cp4(&vb[t * VSTR + 64], gx);
        cp4(&vb[t * VSTR + 65], gx + 1);
        cp4(&vb[t * VSTR + 66], gx + 2);
    }
}

__global__ __launch_bounds__(256, 2) void attn_kernel(const float* __restrict__ xyzs,
                                                      const float* __restrict__ w_sp) {
    extern __shared__ float sm[];
    float* kbuf0 = sm;
    float* kbuf1 = sm + 64 * KSTR;
    float* vbuf0 = sm + 2 * 64 * KSTR;
    float* vbuf1 = vbuf0 + 64 * VSTR;
    float* pb    = vbuf0 + 2 * 64 * VSTR;

    int bh = blockIdx.y;
    int b = bh >> 3, h = bh & 7;
    int i0 = blockIdx.x * 128;
    int t = threadIdx.x;
    int w = t >> 5, lane = t & 31;
    int g = lane >> 2, tq = lane & 3;

    const float* qkvb = g_qkv + (size_t)b * MM * QKVD;
    const float* xyzb = xyzs + (size_t)b * MM * 3;
    const float* kbase = qkvb + INNER + h * DHD;
    const float* vbase = qkvb + 2 * INNER + h * DHD;

    // zero pad cols 67..71 in both V buffers (written once)
    if (t < 128) {
        float* vv = ((t < 64) ? vbuf0 : vbuf1) + (t & 63) * VSTR;
        #pragma unroll
        for (int c = 67; c < 72; c++) vv[c] = 0.f;
    }

    attn_load_stage(kbase, vbase, xyzb, 0, kbuf0, vbuf0, t);
    CP_COMMIT();

    // preload Q fragments (fold in 1/sqrt(64)); overlaps with cp.async stage 0
    unsigned qf[8][4];
    {
        int r0 = i0 + 16 * w + g;
        const float* qp0 = qkvb + (size_t)r0 * QKVD + h * DHD;
        const float* qp1 = qp0 + 8 * QKVD;
        #pragma unroll
        for (int k0 = 0; k0 < 8; k0++) {
            qf[k0][0] = f2u(qp0[8 * k0 + tq]     * 0.125f);
            qf[k0][1] = f2u(qp1[8 * k0 + tq]     * 0.125f);
            qf[k0][2] = f2u(qp0[8 * k0 + tq + 4] * 0.125f);
            qf[k0][3] = f2u(qp1[8 * k0 + tq + 4] * 0.125f);
        }
    }

    float of[9][4] = {};
    float m0 = -1e30f, m1 = -1e30f, l0 = 0.f, l1 = 0.f;
    int pr0 = 16 * w + g, pr1 = pr0 + 8;

    for (int jt = 0; jt < 32; jt++) {
        float* kb = (jt & 1) ? kbuf1 : kbuf0;
        float* vb = (jt & 1) ? vbuf1 : vbuf0;
        if (jt < 31) {
            float* kn = (jt & 1) ? kbuf0 : kbuf1;
            float* vn = (jt & 1) ? vbuf0 : vbuf1;
            attn_load_stage(kbase, vbase, xyzb, (jt + 1) * 64, kn, vn, t);
            CP_COMMIT();
            CP_WAIT(1);
        } else {
            CP_WAIT(0);
        }
        __syncthreads();

        // S = Q K^T
        float sacc[8][4] = {};
        #pragma unroll
        for (int n = 0; n < 8; n++) {
            const float* kbp = &kb[(8 * n + g) * KSTR];
            #pragma unroll
            for (int k0 = 0; k0 < 8; k0++) {
                unsigned b0 = f2u(kbp[8 * k0 + tq]);
                unsigned b1 = f2u(kbp[8 * k0 + tq + 4]);
                mma_tf32(sacc[n], qf[k0][0], qf[k0][1], qf[k0][2], qf[k0][3], b0, b1);
            }
        }

        // online softmax (rows pr0/pr1)
        float lm0 = -1e30f, lm1 = -1e30f;
        #pragma unroll
        for (int n = 0; n < 8; n++) {
            lm0 = fmaxf(lm0, fmaxf(sacc[n][0], sacc[n][1]));
            lm1 = fmaxf(lm1, fmaxf(sacc[n][2], sacc[n][3]));
        }
        #pragma unroll
        for (int o = 1; o < 4; o <<= 1) {
            lm0 = fmaxf(lm0, __shfl_xor_sync(0xffffffffu, lm0, o));
            lm1 = fmaxf(lm1, __shfl_xor_sync(0xffffffffu, lm1, o));
        }
        float mn0 = fmaxf(m0, lm0), mn1 = fmaxf(m1, lm1);
        float al0 = __expf(m0 - mn0), al1 = __expf(m1 - mn1);
        m0 = mn0; m1 = mn1;
        float rs0 = 0.f, rs1 = 0.f;
        #pragma unroll
        for (int n = 0; n < 8; n++) {
            sacc[n][0] = __expf(sacc[n][0] - mn0);
            sacc[n][1] = __expf(sacc[n][1] - mn0);
            sacc[n][2] = __expf(sacc[n][2] - mn1);
            sacc[n][3] = __expf(sacc[n][3] - mn1);
            rs0 += sacc[n][0] + sacc[n][1];
            rs1 += sacc[n][2] + sacc[n][3];
        }
        #pragma unroll
        for (int o = 1; o < 4; o <<= 1) {
            rs0 += __shfl_xor_sync(0xffffffffu, rs0, o);
            rs1 += __shfl_xor_sync(0xffffffffu, rs1, o);
        }
        l0 = l0 * al0 + rs0;
        l1 = l1 * al1 + rs1;
        #pragma unroll
        for (int n = 0; n < 9; n++) {
            of[n][0] *= al0; of[n][1] *= al0;
            of[n][2] *= al1; of[n][3] *= al1;
        }

        // P store (warp-private region, no block sync needed)
        #pragma unroll
        for (int n = 0; n < 8; n++) {
            int col = 8 * n + 2 * tq;
            *(float2*)&pb[pr0 * PSTR + col] = make_float2(sacc[n][0], sacc[n][1]);
            *(float2*)&pb[pr1 * PSTR + col] = make_float2(sacc[n][2], sacc[n][3]);
        }
        __syncwarp();

        // O += P V_ext (cols 64..66 carry attn@xyz)
        #pragma unroll
        for (int k0 = 0; k0 < 8; k0++) {
            unsigned a0 = f2u(pb[pr0 * PSTR + 8 * k0 + tq]);
            unsigned a1 = f2u(pb[pr1 * PSTR + 8 * k0 + tq]);
            unsigned a2 = f2u(pb[pr0 * PSTR + 8 * k0 + tq + 4]);
            unsigned a3 = f2u(pb[pr1 * PSTR + 8 * k0 + tq + 4]);
            const float* vb0 = &vb[(8 * k0 + tq)     * VSTR + g];
            const float* vb1 = &vb[(8 * k0 + tq + 4) * VSTR + g];
            #pragma unroll
            for (int n = 0; n < 9; n++) {
                unsigned b0 = f2u(vb0[8 * n]);
                unsigned b1 = f2u(vb1[8 * n]);
                mma_tf32(of[n], a0, a1, a2, a3, b0, b1);
            }
        }
        __syncthreads();
    }

    // epilogue
    float invl0 = 1.0f / l0, invl1 = 1.0f / l1;
    int base = lane & ~3;
    float ax0_0 = __shfl_sync(0xffffffffu, of[8][0], base + 0);
    float ax1_0 = __shfl_sync(0xffffffffu, of[8][1], base + 0);
    float ax2_0 = __shfl_sync(0xffffffffu, of[8][0], base + 1);
    float ax0_1 = __shfl_sync(0xffffffffu, of[8][2], base + 0);
    float ax1_1 = __shfl_sync(0xffffffffu, of[8][3], base + 0);
    float ax2_1 = __shfl_sync(0xffffffffu, of[8][2], base + 1);

    int row0 = i0 + 16 * w + g, row1 = row0 + 8;
    const float* xq0 = xyzs + ((size_t)b * MM + row0) * 3;
    const float* xq1 = xyzs + ((size_t)b * MM + row1) * 3;
    float a00 = ax0_0 * invl0 - xq0[0];
    float a10 = ax1_0 * invl0 - xq0[1];
    float a20 = ax2_0 * invl0 - xq0[2];
    float a01 = ax0_1 * invl1 - xq1[0];
    float a11 = ax1_1 * invl1 - xq1[1];
    float a21 = ax2_1 * invl1 - xq1[2];

    float* orow0 = g_outpre + ((size_t)b * MM + row0) * INNER + h * DHD;
    float* orow1 = g_outpre + ((size_t)b * MM + row1) * INNER + h * DHD;
    #pragma unroll
    for (int n = 0; n < 8; n++) {
        int d = 8 * n + 2 * tq;
        float w00 = w_sp[d],       w01 = w_sp[d + 1];
        float w10 = w_sp[64 + d],  w11 = w_sp[64 + d + 1];
        float w20 = w_sp[128 + d], w21 = w_sp[128 + d + 1];
        float o00 = of[n][0] * invl0 + a00 * w00 + a10 * w10 + a20 * w20;
        float o01 = of[n][1] * invl0 + a00 * w01 + a10 * w11 + a20 * w21;
        float o10 = of[n][2] * invl1 + a01 * w00 + a11 * w10 + a21 * w20;
        float o11 = of[n][3] * invl1 + a01 * w01 + a11 * w11 + a21 * w21;
        *(float2*)&orow0[d] = make_float2(o00, o01);
        *(float2*)&orow1[d] = make_float2(o10, o11);
    }
}

// ---------------------------------------------------------------- launch
extern "C" void kernel_launch(void* const* d_in, const int* in_sizes, int n_in,
                              void* d_out, int out_size) {
    const float* xyzs     = (const float*)d_in[0];
    const float* features = (const float*)d_in[1];
    const float* gamma    = (const float*)d_in[2];
    const float* beta     = (const float*)d_in[3];
    const float* w_qkv    = (const float*)d_in[4];
    const float* w_sp     = (const float*)d_in[5];
    const float* w_out    = (const float*)d_in[6];
    const float* b_out    = (const float*)d_in[7];
    float* out = (float*)d_out;

    const int g0_smem = 2 * (128 * 36 + 32 * 136) * 4;   // 71680
    const int g1_smem = 2 * (128 * 36 + 32 * 72) * 4;    // 55296
    cudaFuncSetAttribute(gemm_tf32<0, 128>, cudaFuncAttributeMaxDynamicSharedMemorySize, g0_smem);
    cudaFuncSetAttribute(gemm_tf32<1, 64>,  cudaFuncAttributeMaxDynamicSharedMemorySize, g1_smem);
    cudaFuncSetAttribute(attn_kernel, cudaFuncAttributeMaxDynamicSharedMemorySize, ATTN_SMEM);

    ln_kernel<<<ROWS, 256>>>(features, gamma, beta);
    gemm_tf32<0, 128><<<dim3(QKVD / 128, ROWS / 128), 256, g0_smem>>>(w_qkv, nullptr, nullptr, nullptr, QKVD);
    attn_kernel<<<dim3(MM / 128, BB * HEADS), 256, ATTN_SMEM>>>(xyzs, w_sp);
    gemm_tf32<1, 64><<<dim3(DIMF / 64, ROWS / 128), 256, g1_smem>>>(w_out, b_out, features, out, DIMF);
}